// round 2
// baseline (speedup 1.0000x reference)
#include <cuda_runtime.h>
#include <cuda_bf16.h>
#include <cstdint>

// Problem:
// x: [32, 512, 128, 16] f32, W: [16, 512, 512, 2] f32, bias: [16, 512] f32
// out: [32, 512, 128, 32] f32
// Per node n: out[(b,f), (o,k)] += sum_c x[b,c,f,n] * W[n,c,o,k] + bias[n,o]
// i.e. 16 independent GEMMs: A[4096, 512] * B[512, 1024].
//
// Strategy: bf16 3-term split (hi*hi + hi*lo + lo*hi, error ~1e-5) on the
// mma.sync.m16n8k16 HMMA path (tcgen05 is unavailable: harness PTX target is
// sm_103 without the 'a' feature suffix).

#define M_TOTAL    4096   // 32*128
#define K_DIM      512
#define N_PER_NODE 1024
#define NODES      16

// Scratch (device globals; allocation-free per harness rules)
__device__ __nv_bfloat16 g_xh[(size_t)NODES * M_TOTAL * K_DIM];    // [n][m][c] 64MB
__device__ __nv_bfloat16 g_xl[(size_t)NODES * M_TOTAL * K_DIM];    // 64MB
__device__ __nv_bfloat16 g_wh[(size_t)NODES * N_PER_NODE * K_DIM]; // [n][j][c] 16MB
__device__ __nv_bfloat16 g_wl[(size_t)NODES * N_PER_NODE * K_DIM];

static __device__ __forceinline__ uint32_t smem_u32(const void* p) {
    uint32_t a;
    asm("{ .reg .u64 t; cvta.to.shared.u64 t, %1; cvt.u32.u64 %0, t; }"
        : "=r"(a) : "l"(p));
    return a;
}

static __device__ __forceinline__ void cp_async16(uint32_t saddr, const void* gaddr) {
    asm volatile("cp.async.cg.shared.global [%0], [%1], 16;"
                 :: "r"(saddr), "l"(gaddr) : "memory");
}
static __device__ __forceinline__ void cp_commit() {
    asm volatile("cp.async.commit_group;" ::: "memory");
}
template <int N>
static __device__ __forceinline__ void cp_wait() {
    asm volatile("cp.async.wait_group %0;" :: "n"(N) : "memory");
}

static __device__ __forceinline__ void ldsm_x4(uint32_t* r, uint32_t addr) {
    asm volatile("ldmatrix.sync.aligned.m8n8.x4.shared.b16 {%0,%1,%2,%3}, [%4];"
                 : "=r"(r[0]), "=r"(r[1]), "=r"(r[2]), "=r"(r[3]) : "r"(addr));
}

static __device__ __forceinline__ void mma_bf16(float* c, const uint32_t* a,
                                                uint32_t b0, uint32_t b1) {
    asm volatile(
        "mma.sync.aligned.m16n8k16.row.col.f32.bf16.bf16.f32 "
        "{%0,%1,%2,%3}, {%4,%5,%6,%7}, {%8,%9}, {%0,%1,%2,%3};"
        : "+f"(c[0]), "+f"(c[1]), "+f"(c[2]), "+f"(c[3])
        : "r"(a[0]), "r"(a[1]), "r"(a[2]), "r"(a[3]), "r"(b0), "r"(b1));
}

// ---------------------------------------------------------------------------
// Prepass 1: x [b, c, f, n] f32 -> xh/xl [n][m = b*128+f][c] bf16 (split hi/lo)
// grid (16 ctiles, 16 ftiles, 32 b), 256 threads.
// ---------------------------------------------------------------------------
__global__ __launch_bounds__(256) void split_x_kernel(const float* __restrict__ x) {
    __shared__ float s[32][129];
    const int c0 = blockIdx.x * 32;
    const int f0 = blockIdx.y * 8;
    const int b  = blockIdx.z;
    const int tid = threadIdx.x;

    // Coalesced read: for each c, 128 consecutive (f,n) elements are contiguous.
    #pragma unroll
    for (int it = 0; it < 16; it++) {
        int idx = tid + it * 256;
        int c = idx >> 7;
        int fn = idx & 127;  // f_local*16 + n
        s[c][fn] = x[(size_t)b * 1048576 + (size_t)(c0 + c) * 2048 + (size_t)f0 * 16 + fn];
    }
    __syncthreads();

    // Each thread writes 16 consecutive c for one (n, f_local) row.
    const int nf = tid >> 1;       // 0..127
    const int half = tid & 1;      // which 16-c half
    const int fl = nf >> 4;        // 0..7
    const int n = nf & 15;
    const int m = b * 128 + f0 + fl;
    const size_t obase = (size_t)n * ((size_t)M_TOTAL * K_DIM) + (size_t)m * K_DIM
                       + c0 + half * 16;

    __align__(16) __nv_bfloat16 hv[16];
    __align__(16) __nv_bfloat16 lv[16];
    #pragma unroll
    for (int cc = 0; cc < 16; cc++) {
        float v = s[half * 16 + cc][fl * 16 + n];
        __nv_bfloat16 h = __float2bfloat16(v);
        float r = v - __bfloat162float(h);
        hv[cc] = h;
        lv[cc] = __float2bfloat16(r);
    }
    uint4* ph = reinterpret_cast<uint4*>(&g_xh[obase]);
    uint4* pl = reinterpret_cast<uint4*>(&g_xl[obase]);
    ph[0] = reinterpret_cast<uint4*>(hv)[0];
    ph[1] = reinterpret_cast<uint4*>(hv)[1];
    pl[0] = reinterpret_cast<uint4*>(lv)[0];
    pl[1] = reinterpret_cast<uint4*>(lv)[1];
}

// ---------------------------------------------------------------------------
// Prepass 2: W [n][c][j=o*2+k] f32 -> wh/wl [n][j][c] bf16 (transpose + split)
// grid (32 jtiles, 16 ctiles, 16 n), 256 threads, 32x32 tiles.
// ---------------------------------------------------------------------------
__global__ __launch_bounds__(256) void split_w_kernel(const float* __restrict__ W) {
    __shared__ float s[32][33];
    const int j0 = blockIdx.x * 32;
    const int c0 = blockIdx.y * 32;
    const int n  = blockIdx.z;
    const int tid = threadIdx.x;

    #pragma unroll
    for (int it = 0; it < 4; it++) {
        int idx = tid + it * 256;
        int i = idx >> 5;   // c local
        int jj = idx & 31;  // j local
        s[i][jj] = W[(size_t)n * 524288 + (size_t)(c0 + i) * 1024 + j0 + jj];
    }
    __syncthreads();
    #pragma unroll
    for (int it = 0; it < 4; it++) {
        int idx = tid + it * 256;
        int jj = idx >> 5;  // j local
        int i = idx & 31;   // c local
        float v = s[i][jj];
        __nv_bfloat16 h = __float2bfloat16(v);
        float r = v - __bfloat162float(h);
        size_t o = (size_t)n * 524288 + (size_t)(j0 + jj) * 512 + c0 + i;
        g_wh[o] = h;
        g_wl[o] = __float2bfloat16(r);
    }
}

// ---------------------------------------------------------------------------
// GEMM: one CTA per (node, jt, mt): 128(m) x 128(j) tile.
// K' = 3*512 (split terms hi*hi, hi*lo, lo*hi), 24 chunks of 64.
// 3-stage cp.async pipeline; 8 warps as 4(m) x 2(j), warp tile 32m x 64j.
// ---------------------------------------------------------------------------
#define KC       64
#define CHUNKS   24
#define STAGE_BYTES 16384               // 128 rows * 128B
#define SMEM_BYTES  (6 * STAGE_BYTES)   // 3 stages x (A+B) = 96KB

__global__ __launch_bounds__(256, 2) void gemm_kernel(const float* __restrict__ bias,
                                                      float* __restrict__ out) {
    extern __shared__ char smem[];
    const uint32_t sbase = smem_u32(smem);
    const int tid = threadIdx.x;
    const int wid = tid >> 5;
    const int lane = tid & 31;

    const int node = blockIdx.x;  // fastest: 16 node-CTAs co-resident -> L2 write merge
    const int jt = blockIdx.y;    // 0..7
    const int mt = blockIdx.z;    // 0..31

    // Source bases (bf16 element offsets)
    const size_t a_node = (size_t)node * ((size_t)M_TOTAL * K_DIM) + (size_t)mt * 128 * K_DIM;
    const size_t b_node = (size_t)node * ((size_t)N_PER_NODE * K_DIM) + (size_t)jt * 128 * K_DIM;
    const __nv_bfloat16* a_term[3] = {g_xh + a_node, g_xh + a_node, g_xl + a_node};
    const __nv_bfloat16* b_term[3] = {g_wh + b_node, g_wl + b_node, g_wh + b_node};

    // cp.async thread mapping: u = tid + p*256 -> row = u>>3, col16 = u&7
    const int ld_row = tid >> 3;
    const int ld_col = tid & 7;

    auto issue_chunk = [&](int chunk, int stage) {
        const __nv_bfloat16* ap = a_term[chunk >> 3] + (chunk & 7) * KC;
        const __nv_bfloat16* bp = b_term[chunk >> 3] + (chunk & 7) * KC;
        uint32_t sa = sbase + stage * STAGE_BYTES;
        uint32_t sb = sbase + 3 * STAGE_BYTES + stage * STAGE_BYTES;
        #pragma unroll
        for (int p = 0; p < 4; p++) {
            int row = ld_row + p * 32;
            uint32_t soff = (uint32_t)row * 128 + (uint32_t)((ld_col ^ (row & 7)) << 4);
            cp_async16(sa + soff, ap + (size_t)row * K_DIM + ld_col * 8);
            cp_async16(sb + soff, bp + (size_t)row * K_DIM + ld_col * 8);
        }
    };

    // Warp tile: wm in {0,32,64,96}, wj in {0,64}
    const int wm = (wid & 3) * 32;
    const int wj = (wid >> 2) * 64;

    // ldmatrix lane address components (bytes within a stage)
    // A x4: lanes 0-7 (m0-7,k0-7), 8-15 (m8-15,k0-7), 16-23 (m0-7,k8-15), 24-31 (m8-15,k8-15)
    const int a_row0 = wm + (lane & 7) + (lane & 8);      // + mt2*16
    const int a_csel = (lane >> 4) & 1;
    // B x4: lanes 0-7 (n0-7,k0-7), 8-15 (n0-7,k8-15), 16-23 (n8-15,k0-7), 24-31 (n8-15,k8-15)
    const int b_row0 = wj + (lane & 7) + ((lane & 16) >> 1);  // + nt*16
    const int b_csel = (lane >> 3) & 1;

    float acc[2][8][4];
    #pragma unroll
    for (int i = 0; i < 2; i++)
        #pragma unroll
        for (int j = 0; j < 8; j++)
            #pragma unroll
            for (int k = 0; k < 4; k++) acc[i][j][k] = 0.f;

    // Prologue: stages 0,1
    issue_chunk(0, 0); cp_commit();
    issue_chunk(1, 1); cp_commit();

    int stage = 0;
    for (int i = 0; i < CHUNKS; i++) {
        cp_wait<1>();
        __syncthreads();

        uint32_t sa = sbase + stage * STAGE_BYTES;
        uint32_t sb = sbase + 3 * STAGE_BYTES + stage * STAGE_BYTES;

        #pragma unroll
        for (int kk = 0; kk < 4; kk++) {
            uint32_t afrag[2][4];
            uint32_t bfrag[4][4];
            #pragma unroll
            for (int mt2 = 0; mt2 < 2; mt2++) {
                int row = a_row0 + mt2 * 16;
                uint32_t addr = sa + (uint32_t)row * 128
                              + (uint32_t)(((2 * kk + a_csel) ^ (row & 7)) << 4);
                ldsm_x4(afrag[mt2], addr);
            }
            #pragma unroll
            for (int nt = 0; nt < 4; nt++) {
                int row = b_row0 + nt * 16;
                uint32_t addr = sb + (uint32_t)row * 128
                              + (uint32_t)(((2 * kk + b_csel) ^ (row & 7)) << 4);
                ldsm_x4(bfrag[nt], addr);
            }
            #pragma unroll
            for (int mt2 = 0; mt2 < 2; mt2++)
                #pragma unroll
                for (int n8 = 0; n8 < 8; n8++)
                    mma_bf16(acc[mt2][n8], afrag[mt2],
                             bfrag[n8 >> 1][(n8 & 1) * 2], bfrag[n8 >> 1][(n8 & 1) * 2 + 1]);
        }

        __syncthreads();
        if (i + 2 < CHUNKS) issue_chunk(i + 2, (stage + 2) % 3);
        cp_commit();  // commit every iteration (possibly empty) to keep group counts aligned
        stage = (stage + 1) % 3;
    }

    // Epilogue: bias + interleaved scatter.
    // out[b][o][f][node*2 + kk], strides: b 2097152, o 4096, f 32.
    const float* bp = bias + node * 512;
    #pragma unroll
    for (int mt2 = 0; mt2 < 2; mt2++) {
        const int m0 = mt * 128 + wm + mt2 * 16 + (lane >> 2);
        const int m1 = m0 + 8;
        const size_t r0 = (size_t)(m0 >> 7) * 2097152 + (size_t)(m0 & 127) * 32 + node * 2;
        const size_t r1 = (size_t)(m1 >> 7) * 2097152 + (size_t)(m1 & 127) * 32 + node * 2;
        #pragma unroll
        for (int n8 = 0; n8 < 8; n8++) {
            int jg = jt * 128 + wj + n8 * 8 + (lane & 3) * 2;  // even
            int o = jg >> 1;
            float bv = __ldg(bp + o);
            float2 v0 = {acc[mt2][n8][0] + bv, acc[mt2][n8][1] + bv};
            float2 v1 = {acc[mt2][n8][2] + bv, acc[mt2][n8][3] + bv};
            *reinterpret_cast<float2*>(out + r0 + (size_t)o * 4096) = v0;
            *reinterpret_cast<float2*>(out + r1 + (size_t)o * 4096) = v1;
        }
    }
}

// ---------------------------------------------------------------------------
extern "C" void kernel_launch(void* const* d_in, const int* in_sizes, int n_in,
                              void* d_out, int out_size) {
    const float* x = nullptr;
    const float* W = nullptr;
    const float* bias = nullptr;
    for (int i = 0; i < n_in; i++) {
        if (in_sizes[i] == 33554432) x = (const float*)d_in[i];       // 32*512*128*16
        else if (in_sizes[i] == 8388608) W = (const float*)d_in[i];   // 16*512*512*2
        else if (in_sizes[i] == 8192) bias = (const float*)d_in[i];   // 16*512
    }
    float* out = (float*)d_out;

    split_x_kernel<<<dim3(16, 16, 32), 256>>>(x);
    split_w_kernel<<<dim3(32, 16, 16), 256>>>(W);

    cudaFuncSetAttribute(gemm_kernel, cudaFuncAttributeMaxDynamicSharedMemorySize, SMEM_BYTES);
    gemm_kernel<<<dim3(NODES, 8, 32), 256, SMEM_BYTES>>>(bias, out);
}

// round 3
// speedup vs baseline: 1.2700x; 1.2700x over previous
#include <cuda_runtime.h>
#include <cuda_fp16.h>
#include <cstdint>

// Problem:
// x: [32, 512, 128, 16] f32, W: [16, 512, 512, 2] f32, bias: [16, 512] f32
// out: [32, 512, 128, 32] f32
// Per node n: 16 independent GEMMs A[4096, 512] * B[512, 1024] + bias.
//
// Strategy: fp16 2-term split. x = xh + xl (both fp16), w ~ wh (fp16).
// out = xh*wh + xl*wh = x*wh exactly; error = x*(w - wh) ~ 2^-12 rel (~1e-4).
// mma.sync.m16n8k16 f16 path (tcgen05 unavailable: harness targets sm_103
// without the 'a' suffix).

#define M_TOTAL    4096   // 32*128
#define K_DIM      512
#define N_PER_NODE 1024
#define NODES      16

// Scratch (device globals; allocation-free per harness rules)
__device__ __half g_xh[(size_t)NODES * M_TOTAL * K_DIM];    // [n][m][c] 64MB
__device__ __half g_xl[(size_t)NODES * M_TOTAL * K_DIM];    // 64MB
__device__ __half g_wh[(size_t)NODES * N_PER_NODE * K_DIM]; // [n][j][c] 16MB

static __device__ __forceinline__ uint32_t smem_u32(const void* p) {
    uint32_t a;
    asm("{ .reg .u64 t; cvta.to.shared.u64 t, %1; cvt.u32.u64 %0, t; }"
        : "=r"(a) : "l"(p));
    return a;
}

static __device__ __forceinline__ void cp_async16(uint32_t saddr, const void* gaddr) {
    asm volatile("cp.async.cg.shared.global [%0], [%1], 16;"
                 :: "r"(saddr), "l"(gaddr) : "memory");
}
static __device__ __forceinline__ void cp_commit() {
    asm volatile("cp.async.commit_group;" ::: "memory");
}
template <int N>
static __device__ __forceinline__ void cp_wait() {
    asm volatile("cp.async.wait_group %0;" :: "n"(N) : "memory");
}

static __device__ __forceinline__ void ldsm_x4(uint32_t* r, uint32_t addr) {
    asm volatile("ldmatrix.sync.aligned.m8n8.x4.shared.b16 {%0,%1,%2,%3}, [%4];"
                 : "=r"(r[0]), "=r"(r[1]), "=r"(r[2]), "=r"(r[3]) : "r"(addr));
}

static __device__ __forceinline__ void mma_f16(float* c, const uint32_t* a,
                                               uint32_t b0, uint32_t b1) {
    asm volatile(
        "mma.sync.aligned.m16n8k16.row.col.f32.f16.f16.f32 "
        "{%0,%1,%2,%3}, {%4,%5,%6,%7}, {%8,%9}, {%0,%1,%2,%3};"
        : "+f"(c[0]), "+f"(c[1]), "+f"(c[2]), "+f"(c[3])
        : "r"(a[0]), "r"(a[1]), "r"(a[2]), "r"(a[3]), "r"(b0), "r"(b1));
}

// ---------------------------------------------------------------------------
// Prepass 1: x [b, c, f, n] f32 -> xh/xl [n][m = b*128+f][c] fp16 (split hi/lo)
// grid (16 ctiles, 16 ftiles, 32 b), 256 threads.
// ---------------------------------------------------------------------------
__global__ __launch_bounds__(256) void split_x_kernel(const float* __restrict__ x) {
    __shared__ float s[32][129];
    const int c0 = blockIdx.x * 32;
    const int f0 = blockIdx.y * 8;
    const int b  = blockIdx.z;
    const int tid = threadIdx.x;

    // Coalesced read: for each c, 128 consecutive (f,n) elements are contiguous.
    #pragma unroll
    for (int it = 0; it < 16; it++) {
        int idx = tid + it * 256;
        int c = idx >> 7;
        int fn = idx & 127;  // f_local*16 + n
        s[c][fn] = x[(size_t)b * 1048576 + (size_t)(c0 + c) * 2048 + (size_t)f0 * 16 + fn];
    }
    __syncthreads();

    // Each thread writes 16 consecutive c for one (n, f_local) row.
    const int nf = tid >> 1;       // 0..127
    const int half = tid & 1;      // which 16-c half
    const int fl = nf >> 4;        // 0..7
    const int n = nf & 15;
    const int m = b * 128 + f0 + fl;
    const size_t obase = (size_t)n * ((size_t)M_TOTAL * K_DIM) + (size_t)m * K_DIM
                       + c0 + half * 16;

    __align__(16) __half hv[16];
    __align__(16) __half lv[16];
    #pragma unroll
    for (int cc = 0; cc < 16; cc++) {
        float v = s[half * 16 + cc][fl * 16 + n];
        __half h = __float2half_rn(v);
        float r = v - __half2float(h);
        hv[cc] = h;
        lv[cc] = __float2half_rn(r);
    }
    uint4* ph = reinterpret_cast<uint4*>(&g_xh[obase]);
    uint4* pl = reinterpret_cast<uint4*>(&g_xl[obase]);
    ph[0] = reinterpret_cast<uint4*>(hv)[0];
    ph[1] = reinterpret_cast<uint4*>(hv)[1];
    pl[0] = reinterpret_cast<uint4*>(lv)[0];
    pl[1] = reinterpret_cast<uint4*>(lv)[1];
}

// ---------------------------------------------------------------------------
// Prepass 2: W [n][c][j=o*2+k] f32 -> wh [n][j][c] fp16 (transpose + convert)
// grid (32 jtiles, 16 ctiles, 16 n), 256 threads, 32x32 tiles.
// ---------------------------------------------------------------------------
__global__ __launch_bounds__(256) void split_w_kernel(const float* __restrict__ W) {
    __shared__ float s[32][33];
    const int j0 = blockIdx.x * 32;
    const int c0 = blockIdx.y * 32;
    const int n  = blockIdx.z;
    const int tid = threadIdx.x;

    #pragma unroll
    for (int it = 0; it < 4; it++) {
        int idx = tid + it * 256;
        int i = idx >> 5;   // c local
        int jj = idx & 31;  // j local
        s[i][jj] = W[(size_t)n * 524288 + (size_t)(c0 + i) * 1024 + j0 + jj];
    }
    __syncthreads();
    #pragma unroll
    for (int it = 0; it < 4; it++) {
        int idx = tid + it * 256;
        int jj = idx >> 5;  // j local
        int i = idx & 31;   // c local
        size_t o = (size_t)n * 524288 + (size_t)(j0 + jj) * 512 + c0 + i;
        g_wh[o] = __float2half_rn(s[i][jj]);
    }
}

// ---------------------------------------------------------------------------
// GEMM: one CTA per (node, jt, mt): 128(m) x 128(j) tile.
// K' = 2*512 (terms xh*wh, xl*wh), 16 chunks of 64.
// Chunk order term-innermost: consecutive chunks reuse the same B chunk (L2 hot).
// 3-stage cp.async pipeline; 8 warps as 4(m) x 2(j), warp tile 32m x 64j.
// ---------------------------------------------------------------------------
#define KC       64
#define CHUNKS   16
#define STAGE_BYTES 16384               // 128 rows * 128B
#define SMEM_BYTES  (6 * STAGE_BYTES)   // 3 stages x (A+B) = 96KB

__global__ __launch_bounds__(256, 2) void gemm_kernel(const float* __restrict__ bias,
                                                      float* __restrict__ out) {
    extern __shared__ char smem[];
    const uint32_t sbase = smem_u32(smem);
    const int tid = threadIdx.x;
    const int wid = tid >> 5;
    const int lane = tid & 31;

    const int node = blockIdx.x;  // fastest: 16 node-CTAs co-resident -> L2 write merge
    const int jt = blockIdx.y;    // 0..7
    const int mt = blockIdx.z;    // 0..31

    // Source bases (fp16 element offsets)
    const size_t a_node = (size_t)node * ((size_t)M_TOTAL * K_DIM) + (size_t)mt * 128 * K_DIM;
    const size_t b_node = (size_t)node * ((size_t)N_PER_NODE * K_DIM) + (size_t)jt * 128 * K_DIM;
    const __half* a_term[2] = {g_xh + a_node, g_xl + a_node};
    const __half* bbase = g_wh + b_node;

    // cp.async thread mapping: u = tid + p*256 -> row = u>>3, col16 = u&7
    const int ld_row = tid >> 3;
    const int ld_col = tid & 7;

    auto issue_chunk = [&](int chunk, int stage) {
        // term-innermost: term = chunk&1, c-block = chunk>>1 (B identical for both terms)
        const __half* ap = a_term[chunk & 1] + (chunk >> 1) * KC;
        const __half* bp = bbase + (chunk >> 1) * KC;
        uint32_t sa = sbase + stage * STAGE_BYTES;
        uint32_t sb = sbase + 3 * STAGE_BYTES + stage * STAGE_BYTES;
        #pragma unroll
        for (int p = 0; p < 4; p++) {
            int row = ld_row + p * 32;
            uint32_t soff = (uint32_t)row * 128 + (uint32_t)((ld_col ^ (row & 7)) << 4);
            cp_async16(sa + soff, ap + (size_t)row * K_DIM + ld_col * 8);
            cp_async16(sb + soff, bp + (size_t)row * K_DIM + ld_col * 8);
        }
    };

    // Warp tile: wm in {0,32,64,96}, wj in {0,64}
    const int wm = (wid & 3) * 32;
    const int wj = (wid >> 2) * 64;

    // ldmatrix lane address components (bytes within a stage)
    const int a_row0 = wm + (lane & 7) + (lane & 8);          // + mt2*16
    const int a_csel = (lane >> 4) & 1;
    const int b_row0 = wj + (lane & 7) + ((lane & 16) >> 1);  // + nt*16
    const int b_csel = (lane >> 3) & 1;

    float acc[2][8][4];
    #pragma unroll
    for (int i = 0; i < 2; i++)
        #pragma unroll
        for (int j = 0; j < 8; j++)
            #pragma unroll
            for (int k = 0; k < 4; k++) acc[i][j][k] = 0.f;

    // Prologue: stages 0,1
    issue_chunk(0, 0); cp_commit();
    issue_chunk(1, 1); cp_commit();

    int stage = 0;
    for (int i = 0; i < CHUNKS; i++) {
        cp_wait<1>();
        __syncthreads();

        uint32_t sa = sbase + stage * STAGE_BYTES;
        uint32_t sb = sbase + 3 * STAGE_BYTES + stage * STAGE_BYTES;

        #pragma unroll
        for (int kk = 0; kk < 4; kk++) {
            uint32_t afrag[2][4];
            uint32_t bfrag[4][4];
            #pragma unroll
            for (int mt2 = 0; mt2 < 2; mt2++) {
                int row = a_row0 + mt2 * 16;
                uint32_t addr = sa + (uint32_t)row * 128
                              + (uint32_t)(((2 * kk + a_csel) ^ (row & 7)) << 4);
                ldsm_x4(afrag[mt2], addr);
            }
            #pragma unroll
            for (int nt = 0; nt < 4; nt++) {
                int row = b_row0 + nt * 16;
                uint32_t addr = sb + (uint32_t)row * 128
                              + (uint32_t)(((2 * kk + b_csel) ^ (row & 7)) << 4);
                ldsm_x4(bfrag[nt], addr);
            }
            #pragma unroll
            for (int mt2 = 0; mt2 < 2; mt2++)
                #pragma unroll
                for (int n8 = 0; n8 < 8; n8++)
                    mma_f16(acc[mt2][n8], afrag[mt2],
                            bfrag[n8 >> 1][(n8 & 1) * 2], bfrag[n8 >> 1][(n8 & 1) * 2 + 1]);
        }

        __syncthreads();
        if (i + 2 < CHUNKS) issue_chunk(i + 2, (stage + 2) % 3);
        cp_commit();  // commit every iteration to keep group counts aligned
        stage = (stage + 1) % 3;
    }

    // Epilogue: bias + interleaved scatter.
    // out[b][o][f][node*2 + kk], strides: b 2097152, o 4096, f 32.
    const float* bp = bias + node * 512;
    #pragma unroll
    for (int mt2 = 0; mt2 < 2; mt2++) {
        const int m0 = mt * 128 + wm + mt2 * 16 + (lane >> 2);
        const int m1 = m0 + 8;
        const size_t r0 = (size_t)(m0 >> 7) * 2097152 + (size_t)(m0 & 127) * 32 + node * 2;
        const size_t r1 = (size_t)(m1 >> 7) * 2097152 + (size_t)(m1 & 127) * 32 + node * 2;
        #pragma unroll
        for (int n8 = 0; n8 < 8; n8++) {
            int jg = jt * 128 + wj + n8 * 8 + (lane & 3) * 2;  // even j
            int o = jg >> 1;
            float bv = __ldg(bp + o);
            float2 v0 = {acc[mt2][n8][0] + bv, acc[mt2][n8][1] + bv};
            float2 v1 = {acc[mt2][n8][2] + bv, acc[mt2][n8][3] + bv};
            *reinterpret_cast<float2*>(out + r0 + (size_t)o * 4096) = v0;
            *reinterpret_cast<float2*>(out + r1 + (size_t)o * 4096) = v1;
        }
    }
}

// ---------------------------------------------------------------------------
extern "C" void kernel_launch(void* const* d_in, const int* in_sizes, int n_in,
                              void* d_out, int out_size) {
    const float* x = nullptr;
    const float* W = nullptr;
    const float* bias = nullptr;
    for (int i = 0; i < n_in; i++) {
        if (in_sizes[i] == 33554432) x = (const float*)d_in[i];       // 32*512*128*16
        else if (in_sizes[i] == 8388608) W = (const float*)d_in[i];   // 16*512*512*2
        else if (in_sizes[i] == 8192) bias = (const float*)d_in[i];   // 16*512
    }
    float* out = (float*)d_out;

    split_x_kernel<<<dim3(16, 16, 32), 256>>>(x);
    split_w_kernel<<<dim3(32, 16, 16), 256>>>(W);

    cudaFuncSetAttribute(gemm_kernel, cudaFuncAttributeMaxDynamicSharedMemorySize, SMEM_BYTES);
    gemm_kernel<<<dim3(NODES, 8, 32), 256, SMEM_BYTES>>>(bias, out);
}

// round 4
// speedup vs baseline: 1.7193x; 1.3537x over previous
#include <cuda_runtime.h>
#include <cuda_fp16.h>
#include <cstdint>

// Problem:
// x: [32, 512, 128, 16] f32, W: [16, 512, 512, 2] f32, bias: [16, 512] f32
// out: [32, 512, 128, 32] f32
// Per node n: 16 independent GEMMs A[4096, 512] * B[512, 1024] + bias.
//
// Strategy: single fp16 GEMM (x and W both rounded to fp16, fp32 accumulate).
// Measured W-only rounding error was 2.07e-4; adding independent x rounding
// gives ~sqrt(2)*2.07e-4 ~ 2.9e-4 << 1e-3 threshold. The GEMM is HMMA
// issue-bound (~925 FLOP/cyc/SM measured), so halving FLOPs halves time.
// (tcgen05 unavailable: harness PTX targets sm_103 without the 'a' suffix.)

#define M_TOTAL    4096   // 32*128
#define K_DIM      512
#define N_PER_NODE 1024
#define NODES      16

// Scratch (device globals; allocation-free per harness rules)
__device__ __half g_xh[(size_t)NODES * M_TOTAL * K_DIM];    // [n][m][c] 64MB
__device__ __half g_wh[(size_t)NODES * N_PER_NODE * K_DIM]; // [n][j][c] 16MB

static __device__ __forceinline__ uint32_t smem_u32(const void* p) {
    uint32_t a;
    asm("{ .reg .u64 t; cvta.to.shared.u64 t, %1; cvt.u32.u64 %0, t; }"
        : "=r"(a) : "l"(p));
    return a;
}

static __device__ __forceinline__ void cp_async16(uint32_t saddr, const void* gaddr) {
    asm volatile("cp.async.cg.shared.global [%0], [%1], 16;"
                 :: "r"(saddr), "l"(gaddr) : "memory");
}
static __device__ __forceinline__ void cp_commit() {
    asm volatile("cp.async.commit_group;" ::: "memory");
}
template <int N>
static __device__ __forceinline__ void cp_wait() {
    asm volatile("cp.async.wait_group %0;" :: "n"(N) : "memory");
}

static __device__ __forceinline__ void ldsm_x4(uint32_t* r, uint32_t addr) {
    asm volatile("ldmatrix.sync.aligned.m8n8.x4.shared.b16 {%0,%1,%2,%3}, [%4];"
                 : "=r"(r[0]), "=r"(r[1]), "=r"(r[2]), "=r"(r[3]) : "r"(addr));
}

static __device__ __forceinline__ void mma_f16(float* c, const uint32_t* a,
                                               uint32_t b0, uint32_t b1) {
    asm volatile(
        "mma.sync.aligned.m16n8k16.row.col.f32.f16.f16.f32 "
        "{%0,%1,%2,%3}, {%4,%5,%6,%7}, {%8,%9}, {%0,%1,%2,%3};"
        : "+f"(c[0]), "+f"(c[1]), "+f"(c[2]), "+f"(c[3])
        : "r"(a[0]), "r"(a[1]), "r"(a[2]), "r"(a[3]), "r"(b0), "r"(b1));
}

// ---------------------------------------------------------------------------
// Prepass 1: x [b, c, f, n] f32 -> xh [n][m = b*128+f][c] fp16.
// Block: c-tile 32, f-tile 16, one b. Each thread writes 64B contiguous.
// grid (16 ctiles, 8 ftiles, 32 b), 256 threads.
// ---------------------------------------------------------------------------
__global__ __launch_bounds__(256) void split_x_kernel(const float* __restrict__ x) {
    __shared__ float s[32][257];
    const int c0 = blockIdx.x * 32;
    const int f0 = blockIdx.y * 16;
    const int b  = blockIdx.z;
    const int tid = threadIdx.x;

    // Coalesced read: 32 c-rows x 256 (fn) floats, float4 wide.
    const float* src = x + (size_t)b * 1048576 + (size_t)c0 * 2048 + (size_t)f0 * 16;
    #pragma unroll
    for (int it = 0; it < 8; it++) {
        int idx = tid + it * 256;   // 0..2047
        int c = idx >> 6;           // 64 float4 per c-row
        int q = idx & 63;
        float4 v = reinterpret_cast<const float4*>(src + (size_t)c * 2048)[q];
        s[c][q * 4 + 0] = v.x;
        s[c][q * 4 + 1] = v.y;
        s[c][q * 4 + 2] = v.z;
        s[c][q * 4 + 3] = v.w;
    }
    __syncthreads();

    // Write: thread t -> (fl = t>>4, n = t&15), 32 consecutive c (64B).
    const int fl = tid >> 4;
    const int n  = tid & 15;
    const int m  = b * 128 + f0 + fl;
    const size_t obase = (size_t)n * ((size_t)M_TOTAL * K_DIM) + (size_t)m * K_DIM + c0;

    __align__(16) __half hv[32];
    #pragma unroll
    for (int cc = 0; cc < 32; cc++)
        hv[cc] = __float2half_rn(s[cc][fl * 16 + n]);
    uint4* ph = reinterpret_cast<uint4*>(&g_xh[obase]);
    #pragma unroll
    for (int q = 0; q < 4; q++)
        ph[q] = reinterpret_cast<uint4*>(hv)[q];
}

// ---------------------------------------------------------------------------
// Prepass 2: W [n][c][j=o*2+k] f32 -> wh [n][j][c] fp16 (transpose + convert)
// grid (32 jtiles, 16 ctiles, 16 n), 256 threads, 32x32 tiles.
// ---------------------------------------------------------------------------
__global__ __launch_bounds__(256) void split_w_kernel(const float* __restrict__ W) {
    __shared__ float s[32][33];
    const int j0 = blockIdx.x * 32;
    const int c0 = blockIdx.y * 32;
    const int n  = blockIdx.z;
    const int tid = threadIdx.x;

    #pragma unroll
    for (int it = 0; it < 4; it++) {
        int idx = tid + it * 256;
        int i = idx >> 5;   // c local
        int jj = idx & 31;  // j local
        s[i][jj] = W[(size_t)n * 524288 + (size_t)(c0 + i) * 1024 + j0 + jj];
    }
    __syncthreads();
    #pragma unroll
    for (int it = 0; it < 4; it++) {
        int idx = tid + it * 256;
        int jj = idx >> 5;  // j local
        int i = idx & 31;   // c local
        size_t o = (size_t)n * 524288 + (size_t)(j0 + jj) * 512 + c0 + i;
        g_wh[o] = __float2half_rn(s[i][jj]);
    }
}

// ---------------------------------------------------------------------------
// GEMM: one CTA per (node, jt, mt): 128(m) x 128(j) tile. K = 512, 8 chunks
// of 64. 3-stage cp.async pipeline; 8 warps as 4(m) x 2(j), warp 32m x 64j.
// ---------------------------------------------------------------------------
#define KC       64
#define CHUNKS   8
#define STAGE_BYTES 16384               // 128 rows * 128B
#define SMEM_BYTES  (6 * STAGE_BYTES)   // 3 stages x (A+B) = 96KB

__global__ __launch_bounds__(256, 2) void gemm_kernel(const float* __restrict__ bias,
                                                      float* __restrict__ out) {
    extern __shared__ char smem[];
    const uint32_t sbase = smem_u32(smem);
    const int tid = threadIdx.x;
    const int wid = tid >> 5;
    const int lane = tid & 31;

    const int node = blockIdx.x;  // fastest: 16 node-CTAs co-resident -> L2 write merge
    const int jt = blockIdx.y;    // 0..7
    const int mt = blockIdx.z;    // 0..31

    const __half* abase = g_xh + (size_t)node * ((size_t)M_TOTAL * K_DIM)
                        + (size_t)mt * 128 * K_DIM;
    const __half* bbase = g_wh + (size_t)node * ((size_t)N_PER_NODE * K_DIM)
                        + (size_t)jt * 128 * K_DIM;

    // cp.async thread mapping: u = tid + p*256 -> row = u>>3, col16 = u&7
    const int ld_row = tid >> 3;
    const int ld_col = tid & 7;

    auto issue_chunk = [&](int chunk, int stage) {
        const __half* ap = abase + chunk * KC;
        const __half* bp = bbase + chunk * KC;
        uint32_t sa = sbase + stage * STAGE_BYTES;
        uint32_t sb = sbase + 3 * STAGE_BYTES + stage * STAGE_BYTES;
        #pragma unroll
        for (int p = 0; p < 4; p++) {
            int row = ld_row + p * 32;
            uint32_t soff = (uint32_t)row * 128 + (uint32_t)((ld_col ^ (row & 7)) << 4);
            cp_async16(sa + soff, ap + (size_t)row * K_DIM + ld_col * 8);
            cp_async16(sb + soff, bp + (size_t)row * K_DIM + ld_col * 8);
        }
    };

    // Warp tile: wm in {0,32,64,96}, wj in {0,64}
    const int wm = (wid & 3) * 32;
    const int wj = (wid >> 2) * 64;

    const int a_row0 = wm + (lane & 7) + (lane & 8);          // + mt2*16
    const int a_csel = (lane >> 4) & 1;
    const int b_row0 = wj + (lane & 7) + ((lane & 16) >> 1);  // + nt*16
    const int b_csel = (lane >> 3) & 1;

    float acc[2][8][4];
    #pragma unroll
    for (int i = 0; i < 2; i++)
        #pragma unroll
        for (int j = 0; j < 8; j++)
            #pragma unroll
            for (int k = 0; k < 4; k++) acc[i][j][k] = 0.f;

    // Prologue: stages 0,1
    issue_chunk(0, 0); cp_commit();
    issue_chunk(1, 1); cp_commit();

    int stage = 0;
    for (int i = 0; i < CHUNKS; i++) {
        cp_wait<1>();
        __syncthreads();

        uint32_t sa = sbase + stage * STAGE_BYTES;
        uint32_t sb = sbase + 3 * STAGE_BYTES + stage * STAGE_BYTES;

        #pragma unroll
        for (int kk = 0; kk < 4; kk++) {
            uint32_t afrag[2][4];
            uint32_t bfrag[4][4];
            #pragma unroll
            for (int mt2 = 0; mt2 < 2; mt2++) {
                int row = a_row0 + mt2 * 16;
                uint32_t addr = sa + (uint32_t)row * 128
                              + (uint32_t)(((2 * kk + a_csel) ^ (row & 7)) << 4);
                ldsm_x4(afrag[mt2], addr);
            }
            #pragma unroll
            for (int nt = 0; nt < 4; nt++) {
                int row = b_row0 + nt * 16;
                uint32_t addr = sb + (uint32_t)row * 128
                              + (uint32_t)(((2 * kk + b_csel) ^ (row & 7)) << 4);
                ldsm_x4(bfrag[nt], addr);
            }
            #pragma unroll
            for (int mt2 = 0; mt2 < 2; mt2++)
                #pragma unroll
                for (int n8 = 0; n8 < 8; n8++)
                    mma_f16(acc[mt2][n8], afrag[mt2],
                            bfrag[n8 >> 1][(n8 & 1) * 2], bfrag[n8 >> 1][(n8 & 1) * 2 + 1]);
        }

        __syncthreads();
        if (i + 2 < CHUNKS) issue_chunk(i + 2, (stage + 2) % 3);
        cp_commit();  // commit every iteration to keep group counts aligned
        stage = (stage + 1) % 3;
    }

    // Epilogue: bias + interleaved scatter.
    // out[b][o][f][node*2 + kk], strides: b 2097152, o 4096, f 32.
    const float* bp = bias + node * 512;
    #pragma unroll
    for (int mt2 = 0; mt2 < 2; mt2++) {
        const int m0 = mt * 128 + wm + mt2 * 16 + (lane >> 2);
        const int m1 = m0 + 8;
        const size_t r0 = (size_t)(m0 >> 7) * 2097152 + (size_t)(m0 & 127) * 32 + node * 2;
        const size_t r1 = (size_t)(m1 >> 7) * 2097152 + (size_t)(m1 & 127) * 32 + node * 2;
        #pragma unroll
        for (int n8 = 0; n8 < 8; n8++) {
            int jg = jt * 128 + wj + n8 * 8 + (lane & 3) * 2;  // even j
            int o = jg >> 1;
            float bv = __ldg(bp + o);
            float2 v0 = {acc[mt2][n8][0] + bv, acc[mt2][n8][1] + bv};
            float2 v1 = {acc[mt2][n8][2] + bv, acc[mt2][n8][3] + bv};
            *reinterpret_cast<float2*>(out + r0 + (size_t)o * 4096) = v0;
            *reinterpret_cast<float2*>(out + r1 + (size_t)o * 4096) = v1;
        }
    }
}

// ---------------------------------------------------------------------------
extern "C" void kernel_launch(void* const* d_in, const int* in_sizes, int n_in,
                              void* d_out, int out_size) {
    const float* x = nullptr;
    const float* W = nullptr;
    const float* bias = nullptr;
    for (int i = 0; i < n_in; i++) {
        if (in_sizes[i] == 33554432) x = (const float*)d_in[i];       // 32*512*128*16
        else if (in_sizes[i] == 8388608) W = (const float*)d_in[i];   // 16*512*512*2
        else if (in_sizes[i] == 8192) bias = (const float*)d_in[i];   // 16*512
    }
    float* out = (float*)d_out;

    split_x_kernel<<<dim3(16, 8, 32), 256>>>(x);
    split_w_kernel<<<dim3(32, 16, 16), 256>>>(W);

    cudaFuncSetAttribute(gemm_kernel, cudaFuncAttributeMaxDynamicSharedMemorySize, SMEM_BYTES);
    gemm_kernel<<<dim3(NODES, 8, 32), 256, SMEM_BYTES>>>(bias, out);
}

// round 5
// speedup vs baseline: 2.3203x; 1.3495x over previous
#include <cuda_runtime.h>
#include <cuda_fp16.h>
#include <cstdint>

// Problem:
// x: [32, 512, 128, 16] f32, W: [16, 512, 512, 2] f32, bias: [16, 512] f32
// out: [32, 512, 128, 32] f32
// Per node n: 16 independent GEMMs A[4096, 512] * B[512, 1024] + bias.
//
// fp16 single-GEMM (rel_err ~2.9e-4 measured, threshold 1e-3).
// Pipeline: split_x (transpose x -> [n][m][c] fp16), split_w (transpose W ->
// [n][j][c] fp16), HMMA GEMM -> dense scratch y[n][m][j] f32 (coalesced),
// repack (gather 16 nodes per 128B out sector + bias, fully coalesced).

#define M_TOTAL    4096   // 32*128
#define K_DIM      512
#define N_PER_NODE 1024
#define NODES      16

__device__ __half g_xh[(size_t)NODES * M_TOTAL * K_DIM];    // [n][m][c] 64MB
__device__ __half g_wh[(size_t)NODES * N_PER_NODE * K_DIM]; // [n][j][c] 16MB
__device__ float  g_y[(size_t)NODES * M_TOTAL * N_PER_NODE]; // [n][m][j] 268MB

static __device__ __forceinline__ uint32_t smem_u32(const void* p) {
    uint32_t a;
    asm("{ .reg .u64 t; cvta.to.shared.u64 t, %1; cvt.u32.u64 %0, t; }"
        : "=r"(a) : "l"(p));
    return a;
}

static __device__ __forceinline__ void cp_async16(uint32_t saddr, const void* gaddr) {
    asm volatile("cp.async.cg.shared.global [%0], [%1], 16;"
                 :: "r"(saddr), "l"(gaddr) : "memory");
}
static __device__ __forceinline__ void cp_commit() {
    asm volatile("cp.async.commit_group;" ::: "memory");
}
template <int N>
static __device__ __forceinline__ void cp_wait() {
    asm volatile("cp.async.wait_group %0;" :: "n"(N) : "memory");
}

static __device__ __forceinline__ void ldsm_x4(uint32_t* r, uint32_t addr) {
    asm volatile("ldmatrix.sync.aligned.m8n8.x4.shared.b16 {%0,%1,%2,%3}, [%4];"
                 : "=r"(r[0]), "=r"(r[1]), "=r"(r[2]), "=r"(r[3]) : "r"(addr));
}

static __device__ __forceinline__ void mma_f16(float* c, const uint32_t* a,
                                               uint32_t b0, uint32_t b1) {
    asm volatile(
        "mma.sync.aligned.m16n8k16.row.col.f32.f16.f16.f32 "
        "{%0,%1,%2,%3}, {%4,%5,%6,%7}, {%8,%9}, {%0,%1,%2,%3};"
        : "+f"(c[0]), "+f"(c[1]), "+f"(c[2]), "+f"(c[3])
        : "r"(a[0]), "r"(a[1]), "r"(a[2]), "r"(a[3]), "r"(b0), "r"(b1));
}

// ---------------------------------------------------------------------------
// Prepass 1: x [b, c, f, n] f32 -> xh [n][m = b*128+f][c] fp16.
// c-tile 64, f-tile 8: lane-pairs cover full 128B output lines.
// grid (8 ctiles, 16 ftiles, 32 b), 256 threads.
// ---------------------------------------------------------------------------
__global__ __launch_bounds__(256) void split_x_kernel(const float* __restrict__ x) {
    __shared__ float s[64][132];
    const int c0 = blockIdx.x * 64;
    const int f0 = blockIdx.y * 8;
    const int b  = blockIdx.z;
    const int tid = threadIdx.x;

    // Read: 64 c-rows x 128 (fn) floats, float4 wide, fully coalesced.
    const float* src = x + (size_t)b * 1048576 + (size_t)c0 * 2048 + (size_t)f0 * 16;
    #pragma unroll
    for (int it = 0; it < 8; it++) {
        int idx = tid + it * 256;   // 0..2047
        int c = idx >> 5;           // 32 float4 per c-row
        int q = idx & 31;
        float4 v = reinterpret_cast<const float4*>(src + (size_t)c * 2048)[q];
        *reinterpret_cast<float4*>(&s[c][q * 4]) = v;
    }
    __syncthreads();

    // Write: thread pair (t, t^1) covers one (n, fl) row's 64 c = 128B line.
    const int row  = tid >> 1;     // 0..127
    const int half = tid & 1;
    const int fl = row >> 4;       // 0..7
    const int n  = row & 15;
    const int m  = b * 128 + f0 + fl;
    const size_t obase = (size_t)n * ((size_t)M_TOTAL * K_DIM) + (size_t)m * K_DIM
                       + c0 + half * 32;

    __align__(16) __half hv[32];
    #pragma unroll
    for (int cc = 0; cc < 32; cc++)
        hv[cc] = __float2half_rn(s[half * 32 + cc][fl * 16 + n]);
    uint4* ph = reinterpret_cast<uint4*>(&g_xh[obase]);
    #pragma unroll
    for (int q = 0; q < 4; q++)
        ph[q] = reinterpret_cast<uint4*>(hv)[q];
}

// ---------------------------------------------------------------------------
// Prepass 2: W [n][c][j=o*2+k] f32 -> wh [n][j][c] fp16 (transpose + convert)
// grid (32 jtiles, 16 ctiles, 16 n), 256 threads, 32x32 tiles.
// ---------------------------------------------------------------------------
__global__ __launch_bounds__(256) void split_w_kernel(const float* __restrict__ W) {
    __shared__ float s[32][33];
    const int j0 = blockIdx.x * 32;
    const int c0 = blockIdx.y * 32;
    const int n  = blockIdx.z;
    const int tid = threadIdx.x;

    #pragma unroll
    for (int it = 0; it < 4; it++) {
        int idx = tid + it * 256;
        int i = idx >> 5;   // c local
        int jj = idx & 31;  // j local
        s[i][jj] = W[(size_t)n * 524288 + (size_t)(c0 + i) * 1024 + j0 + jj];
    }
    __syncthreads();
    #pragma unroll
    for (int it = 0; it < 4; it++) {
        int idx = tid + it * 256;
        int jj = idx >> 5;  // j local
        int i = idx & 31;   // c local
        size_t o = (size_t)n * 524288 + (size_t)(j0 + jj) * 512 + c0 + i;
        g_wh[o] = __float2half_rn(s[i][jj]);
    }
}

// ---------------------------------------------------------------------------
// GEMM: one CTA per (node, jt, mt): 128(m) x 128(j) tile. K = 512, 8 chunks
// of 64. 3-stage cp.async pipeline; 8 warps 4(m) x 2(j), warp 32m x 64j.
// Output: dense scratch y[n][m][j] (coalesced; bias/scatter moved to repack).
// ---------------------------------------------------------------------------
#define KC       64
#define CHUNKS   8
#define STAGE_BYTES 16384               // 128 rows * 128B
#define SMEM_BYTES  (6 * STAGE_BYTES)   // 3 stages x (A+B) = 96KB

__global__ __launch_bounds__(256, 2) void gemm_kernel() {
    extern __shared__ char smem[];
    const uint32_t sbase = smem_u32(smem);
    const int tid = threadIdx.x;
    const int wid = tid >> 5;
    const int lane = tid & 31;

    const int node = blockIdx.x;
    const int jt = blockIdx.y;    // 0..7
    const int mt = blockIdx.z;    // 0..31

    const __half* abase = g_xh + (size_t)node * ((size_t)M_TOTAL * K_DIM)
                        + (size_t)mt * 128 * K_DIM;
    const __half* bbase = g_wh + (size_t)node * ((size_t)N_PER_NODE * K_DIM)
                        + (size_t)jt * 128 * K_DIM;

    const int ld_row = tid >> 3;
    const int ld_col = tid & 7;

    auto issue_chunk = [&](int chunk, int stage) {
        const __half* ap = abase + chunk * KC;
        const __half* bp = bbase + chunk * KC;
        uint32_t sa = sbase + stage * STAGE_BYTES;
        uint32_t sb = sbase + 3 * STAGE_BYTES + stage * STAGE_BYTES;
        #pragma unroll
        for (int p = 0; p < 4; p++) {
            int row = ld_row + p * 32;
            uint32_t soff = (uint32_t)row * 128 + (uint32_t)((ld_col ^ (row & 7)) << 4);
            cp_async16(sa + soff, ap + (size_t)row * K_DIM + ld_col * 8);
            cp_async16(sb + soff, bp + (size_t)row * K_DIM + ld_col * 8);
        }
    };

    const int wm = (wid & 3) * 32;
    const int wj = (wid >> 2) * 64;

    const int a_row0 = wm + (lane & 7) + (lane & 8);          // + mt2*16
    const int a_csel = (lane >> 4) & 1;
    const int b_row0 = wj + (lane & 7) + ((lane & 16) >> 1);  // + nt*16
    const int b_csel = (lane >> 3) & 1;

    float acc[2][8][4];
    #pragma unroll
    for (int i = 0; i < 2; i++)
        #pragma unroll
        for (int j = 0; j < 8; j++)
            #pragma unroll
            for (int k = 0; k < 4; k++) acc[i][j][k] = 0.f;

    issue_chunk(0, 0); cp_commit();
    issue_chunk(1, 1); cp_commit();

    int stage = 0;
    for (int i = 0; i < CHUNKS; i++) {
        cp_wait<1>();
        __syncthreads();

        uint32_t sa = sbase + stage * STAGE_BYTES;
        uint32_t sb = sbase + 3 * STAGE_BYTES + stage * STAGE_BYTES;

        #pragma unroll
        for (int kk = 0; kk < 4; kk++) {
            uint32_t afrag[2][4];
            uint32_t bfrag[4][4];
            #pragma unroll
            for (int mt2 = 0; mt2 < 2; mt2++) {
                int row = a_row0 + mt2 * 16;
                uint32_t addr = sa + (uint32_t)row * 128
                              + (uint32_t)(((2 * kk + a_csel) ^ (row & 7)) << 4);
                ldsm_x4(afrag[mt2], addr);
            }
            #pragma unroll
            for (int nt = 0; nt < 4; nt++) {
                int row = b_row0 + nt * 16;
                uint32_t addr = sb + (uint32_t)row * 128
                              + (uint32_t)(((2 * kk + b_csel) ^ (row & 7)) << 4);
                ldsm_x4(bfrag[nt], addr);
            }
            #pragma unroll
            for (int mt2 = 0; mt2 < 2; mt2++)
                #pragma unroll
                for (int n8 = 0; n8 < 8; n8++)
                    mma_f16(acc[mt2][n8], afrag[mt2],
                            bfrag[n8 >> 1][(n8 & 1) * 2], bfrag[n8 >> 1][(n8 & 1) * 2 + 1]);
        }

        __syncthreads();
        if (i + 2 < CHUNKS) issue_chunk(i + 2, (stage + 2) % 3);
        cp_commit();
        stage = (stage + 1) % 3;
    }

    // Epilogue: dense write to y[node][m][j]. Lane groups are 32B-contiguous;
    // the n8 loop fills full 128B lines -> coalesced, no scatter.
    float* ybase = g_y + ((size_t)node * M_TOTAL + (size_t)mt * 128) * N_PER_NODE
                 + jt * 128;
    #pragma unroll
    for (int mt2 = 0; mt2 < 2; mt2++) {
        const int ml = wm + mt2 * 16 + (lane >> 2);
        float* r0 = ybase + (size_t)ml * N_PER_NODE;
        float* r1 = ybase + (size_t)(ml + 8) * N_PER_NODE;
        #pragma unroll
        for (int n8 = 0; n8 < 8; n8++) {
            int j = wj + n8 * 8 + (lane & 3) * 2;
            float2 v0 = {acc[mt2][n8][0], acc[mt2][n8][1]};
            float2 v1 = {acc[mt2][n8][2], acc[mt2][n8][3]};
            *reinterpret_cast<float2*>(r0 + j) = v0;
            *reinterpret_cast<float2*>(r1 + j) = v1;
        }
    }
}

// ---------------------------------------------------------------------------
// Repack: out[b][o][f][n*2+k] = y[n][b*128+f][o*2+k] + bias[n][o].
// Block tile: b fixed, f-tile 16, o-tile 16 (j-tile 32). Reads y in 128B
// lines (lane<->j), smem pitch 273 (=17 mod 32, conflict-free STS), writes
// out as full float4 / 128B-per-4-lane-group coalesced stores.
// grid (32 otiles, 8 ftiles, 32 b), 256 threads.
// ---------------------------------------------------------------------------
__global__ __launch_bounds__(256) void repack_kernel(const float* __restrict__ bias,
                                                     float* __restrict__ out) {
    __shared__ float s[8734];   // s[jl*273 + f*17 + n], jl<32, f<16, n<16
    const int o0 = blockIdx.x * 16;
    const int j0 = o0 * 2;
    const int f0 = blockIdx.y * 16;
    const int b  = blockIdx.z;
    const int tid = threadIdx.x;

    const size_t ynode = (size_t)M_TOTAL * N_PER_NODE;

    #pragma unroll
    for (int p = 0; p < 32; p++) {
        int idx = p * 256 + tid;      // 0..8191
        int n = idx >> 9;             // 16 f x 32 j per n
        int f = (idx >> 5) & 15;
        int jl = tid & 31;
        s[jl * 273 + f * 17 + n] =
            g_y[n * ynode + ((size_t)b * 128 + f0 + f) * N_PER_NODE + j0 + jl];
    }
    __syncthreads();

    #pragma unroll
    for (int p = 0; p < 8; p++) {
        int idx = p * 256 + tid;      // 0..2047
        int ol = idx >> 7;            // 0..15
        int f = (idx >> 3) & 15;
        int g = idx & 7;
        int n0 = 2 * g;
        int jl = 2 * ol;
        float b0 = __ldg(bias + n0 * 512 + o0 + ol);
        float b1 = __ldg(bias + (n0 + 1) * 512 + o0 + ol);
        float4 v;
        v.x = s[jl * 273 + f * 17 + n0] + b0;
        v.y = s[(jl + 1) * 273 + f * 17 + n0] + b0;
        v.z = s[jl * 273 + f * 17 + n0 + 1] + b1;
        v.w = s[(jl + 1) * 273 + f * 17 + n0 + 1] + b1;
        size_t oaddr = (size_t)b * 2097152 + (size_t)(o0 + ol) * 4096
                     + (size_t)(f0 + f) * 32 + g * 4;
        *reinterpret_cast<float4*>(out + oaddr) = v;
    }
}

// ---------------------------------------------------------------------------
extern "C" void kernel_launch(void* const* d_in, const int* in_sizes, int n_in,
                              void* d_out, int out_size) {
    const float* x = nullptr;
    const float* W = nullptr;
    const float* bias = nullptr;
    for (int i = 0; i < n_in; i++) {
        if (in_sizes[i] == 33554432) x = (const float*)d_in[i];       // 32*512*128*16
        else if (in_sizes[i] == 8388608) W = (const float*)d_in[i];   // 16*512*512*2
        else if (in_sizes[i] == 8192) bias = (const float*)d_in[i];   // 16*512
    }
    float* out = (float*)d_out;

    split_x_kernel<<<dim3(8, 16, 32), 256>>>(x);
    split_w_kernel<<<dim3(32, 16, 16), 256>>>(W);

    cudaFuncSetAttribute(gemm_kernel, cudaFuncAttributeMaxDynamicSharedMemorySize, SMEM_BYTES);
    gemm_kernel<<<dim3(NODES, 8, 32), 256, SMEM_BYTES>>>();

    repack_kernel<<<dim3(32, 8, 32), 256>>>(bias, out);
}

// round 6
// speedup vs baseline: 2.4165x; 1.0415x over previous
#include <cuda_runtime.h>
#include <cuda_fp16.h>
#include <cstdint>

// Problem:
// x: [32, 512, 128, 16] f32, W: [16, 512, 512, 2] f32, bias: [16, 512] f32
// out: [32, 512, 128, 32] f32
// Per node n: 16 independent GEMMs A[4096, 512] * B[512, 1024] + bias.
//
// fp16 single-GEMM + fp16 intermediate y (rel_err budget ~4.1e-4 < 1e-3).
// Pipeline: split_x (x -> [n][m][c] fp16), split_w (W -> [n][j][c] fp16),
// HMMA GEMM -> y[n][m][j] fp16 (134MB, ~fits L2), repack (gather 16 nodes
// per 128B out sector + fp32 bias, coalesced, b-reversed for L2 residency).

#define M_TOTAL    4096   // 32*128
#define K_DIM      512
#define N_PER_NODE 1024
#define NODES      16

__device__ __half g_xh[(size_t)NODES * M_TOTAL * K_DIM];     // [n][m][c] 64MB
__device__ __half g_wh[(size_t)NODES * N_PER_NODE * K_DIM];  // [n][j][c] 16MB
__device__ __half g_yh[(size_t)NODES * M_TOTAL * N_PER_NODE]; // [n][m][j] 134MB

static __device__ __forceinline__ uint32_t smem_u32(const void* p) {
    uint32_t a;
    asm("{ .reg .u64 t; cvta.to.shared.u64 t, %1; cvt.u32.u64 %0, t; }"
        : "=r"(a) : "l"(p));
    return a;
}

static __device__ __forceinline__ void cp_async16(uint32_t saddr, const void* gaddr) {
    asm volatile("cp.async.cg.shared.global [%0], [%1], 16;"
                 :: "r"(saddr), "l"(gaddr) : "memory");
}
static __device__ __forceinline__ void cp_commit() {
    asm volatile("cp.async.commit_group;" ::: "memory");
}
template <int N>
static __device__ __forceinline__ void cp_wait() {
    asm volatile("cp.async.wait_group %0;" :: "n"(N) : "memory");
}

static __device__ __forceinline__ void ldsm_x4(uint32_t* r, uint32_t addr) {
    asm volatile("ldmatrix.sync.aligned.m8n8.x4.shared.b16 {%0,%1,%2,%3}, [%4];"
                 : "=r"(r[0]), "=r"(r[1]), "=r"(r[2]), "=r"(r[3]) : "r"(addr));
}

static __device__ __forceinline__ void mma_f16(float* c, const uint32_t* a,
                                               uint32_t b0, uint32_t b1) {
    asm volatile(
        "mma.sync.aligned.m16n8k16.row.col.f32.f16.f16.f32 "
        "{%0,%1,%2,%3}, {%4,%5,%6,%7}, {%8,%9}, {%0,%1,%2,%3};"
        : "+f"(c[0]), "+f"(c[1]), "+f"(c[2]), "+f"(c[3])
        : "r"(a[0]), "r"(a[1]), "r"(a[2]), "r"(a[3]), "r"(b0), "r"(b1));
}

// ---------------------------------------------------------------------------
// Prepass 1: x [b, c, f, n] f32 -> xh [n][m = b*128+f][c] fp16.
// c-tile 64, f-tile 8: lane-pairs cover full 128B output lines.
// grid (8 ctiles, 16 ftiles, 32 b), 256 threads.
// ---------------------------------------------------------------------------
__global__ __launch_bounds__(256) void split_x_kernel(const float* __restrict__ x) {
    __shared__ float s[64][132];
    const int c0 = blockIdx.x * 64;
    const int f0 = blockIdx.y * 8;
    const int b  = blockIdx.z;
    const int tid = threadIdx.x;

    const float* src = x + (size_t)b * 1048576 + (size_t)c0 * 2048 + (size_t)f0 * 16;
    #pragma unroll
    for (int it = 0; it < 8; it++) {
        int idx = tid + it * 256;   // 0..2047
        int c = idx >> 5;           // 32 float4 per c-row
        int q = idx & 31;
        float4 v = reinterpret_cast<const float4*>(src + (size_t)c * 2048)[q];
        *reinterpret_cast<float4*>(&s[c][q * 4]) = v;
    }
    __syncthreads();

    const int row  = tid >> 1;     // 0..127
    const int half = tid & 1;
    const int fl = row >> 4;       // 0..7
    const int n  = row & 15;
    const int m  = b * 128 + f0 + fl;
    const size_t obase = (size_t)n * ((size_t)M_TOTAL * K_DIM) + (size_t)m * K_DIM
                       + c0 + half * 32;

    __align__(16) __half hv[32];
    #pragma unroll
    for (int cc = 0; cc < 32; cc++)
        hv[cc] = __float2half_rn(s[half * 32 + cc][fl * 16 + n]);
    uint4* ph = reinterpret_cast<uint4*>(&g_xh[obase]);
    #pragma unroll
    for (int q = 0; q < 4; q++)
        ph[q] = reinterpret_cast<uint4*>(hv)[q];
}

// ---------------------------------------------------------------------------
// Prepass 2: W [n][c][j=o*2+k] f32 -> wh [n][j][c] fp16 (transpose + convert)
// grid (32 jtiles, 16 ctiles, 16 n), 256 threads, 32x32 tiles.
// ---------------------------------------------------------------------------
__global__ __launch_bounds__(256) void split_w_kernel(const float* __restrict__ W) {
    __shared__ float s[32][33];
    const int j0 = blockIdx.x * 32;
    const int c0 = blockIdx.y * 32;
    const int n  = blockIdx.z;
    const int tid = threadIdx.x;

    #pragma unroll
    for (int it = 0; it < 4; it++) {
        int idx = tid + it * 256;
        int i = idx >> 5;   // c local
        int jj = idx & 31;  // j local
        s[i][jj] = W[(size_t)n * 524288 + (size_t)(c0 + i) * 1024 + j0 + jj];
    }
    __syncthreads();
    #pragma unroll
    for (int it = 0; it < 4; it++) {
        int idx = tid + it * 256;
        int jj = idx >> 5;  // j local
        int i = idx & 31;   // c local
        size_t o = (size_t)n * 524288 + (size_t)(j0 + jj) * 512 + c0 + i;
        g_wh[o] = __float2half_rn(s[i][jj]);
    }
}

// ---------------------------------------------------------------------------
// GEMM: one CTA per (node, jt, b): 128(m) x 128(j) tile. K = 512, 8 chunks
// of 64. 3-stage cp.async pipeline; 8 warps 4(m) x 2(j), warp 32m x 64j.
// Output: dense fp16 scratch y[n][m][j] (coalesced half2 stores).
// ---------------------------------------------------------------------------
#define KC       64
#define CHUNKS   8
#define STAGE_BYTES 16384               // 128 rows * 128B
#define SMEM_BYTES  (6 * STAGE_BYTES)   // 3 stages x (A+B) = 96KB

__global__ __launch_bounds__(256, 2) void gemm_kernel() {
    extern __shared__ char smem[];
    const uint32_t sbase = smem_u32(smem);
    const int tid = threadIdx.x;
    const int wid = tid >> 5;
    const int lane = tid & 31;

    const int node = blockIdx.x;
    const int jt = blockIdx.y;    // 0..7
    const int mt = blockIdx.z;    // 0..31 (== b)

    const __half* abase = g_xh + (size_t)node * ((size_t)M_TOTAL * K_DIM)
                        + (size_t)mt * 128 * K_DIM;
    const __half* bbase = g_wh + (size_t)node * ((size_t)N_PER_NODE * K_DIM)
                        + (size_t)jt * 128 * K_DIM;

    const int ld_row = tid >> 3;
    const int ld_col = tid & 7;

    auto issue_chunk = [&](int chunk, int stage) {
        const __half* ap = abase + chunk * KC;
        const __half* bp = bbase + chunk * KC;
        uint32_t sa = sbase + stage * STAGE_BYTES;
        uint32_t sb = sbase + 3 * STAGE_BYTES + stage * STAGE_BYTES;
        #pragma unroll
        for (int p = 0; p < 4; p++) {
            int row = ld_row + p * 32;
            uint32_t soff = (uint32_t)row * 128 + (uint32_t)((ld_col ^ (row & 7)) << 4);
            cp_async16(sa + soff, ap + (size_t)row * K_DIM + ld_col * 8);
            cp_async16(sb + soff, bp + (size_t)row * K_DIM + ld_col * 8);
        }
    };

    const int wm = (wid & 3) * 32;
    const int wj = (wid >> 2) * 64;

    const int a_row0 = wm + (lane & 7) + (lane & 8);          // + mt2*16
    const int a_csel = (lane >> 4) & 1;
    const int b_row0 = wj + (lane & 7) + ((lane & 16) >> 1);  // + nt*16
    const int b_csel = (lane >> 3) & 1;

    float acc[2][8][4];
    #pragma unroll
    for (int i = 0; i < 2; i++)
        #pragma unroll
        for (int j = 0; j < 8; j++)
            #pragma unroll
            for (int k = 0; k < 4; k++) acc[i][j][k] = 0.f;

    issue_chunk(0, 0); cp_commit();
    issue_chunk(1, 1); cp_commit();

    int stage = 0;
    for (int i = 0; i < CHUNKS; i++) {
        cp_wait<1>();
        __syncthreads();

        uint32_t sa = sbase + stage * STAGE_BYTES;
        uint32_t sb = sbase + 3 * STAGE_BYTES + stage * STAGE_BYTES;

        #pragma unroll
        for (int kk = 0; kk < 4; kk++) {
            uint32_t afrag[2][4];
            uint32_t bfrag[4][4];
            #pragma unroll
            for (int mt2 = 0; mt2 < 2; mt2++) {
                int row = a_row0 + mt2 * 16;
                uint32_t addr = sa + (uint32_t)row * 128
                              + (uint32_t)(((2 * kk + a_csel) ^ (row & 7)) << 4);
                ldsm_x4(afrag[mt2], addr);
            }
            #pragma unroll
            for (int nt = 0; nt < 4; nt++) {
                int row = b_row0 + nt * 16;
                uint32_t addr = sb + (uint32_t)row * 128
                              + (uint32_t)(((2 * kk + b_csel) ^ (row & 7)) << 4);
                ldsm_x4(bfrag[nt], addr);
            }
            #pragma unroll
            for (int mt2 = 0; mt2 < 2; mt2++)
                #pragma unroll
                for (int n8 = 0; n8 < 8; n8++)
                    mma_f16(acc[mt2][n8], afrag[mt2],
                            bfrag[n8 >> 1][(n8 & 1) * 2], bfrag[n8 >> 1][(n8 & 1) * 2 + 1]);
        }

        __syncthreads();
        if (i + 2 < CHUNKS) issue_chunk(i + 2, (stage + 2) % 3);
        cp_commit();
        stage = (stage + 1) % 3;
    }

    // Epilogue: dense fp16 write to y[node][m][j], coalesced half2 stores.
    __half* ybase = g_yh + ((size_t)node * M_TOTAL + (size_t)mt * 128) * N_PER_NODE
                  + jt * 128;
    #pragma unroll
    for (int mt2 = 0; mt2 < 2; mt2++) {
        const int ml = wm + mt2 * 16 + (lane >> 2);
        __half* r0 = ybase + (size_t)ml * N_PER_NODE;
        __half* r1 = ybase + (size_t)(ml + 8) * N_PER_NODE;
        #pragma unroll
        for (int n8 = 0; n8 < 8; n8++) {
            int j = wj + n8 * 8 + (lane & 3) * 2;
            *reinterpret_cast<__half2*>(r0 + j) =
                __floats2half2_rn(acc[mt2][n8][0], acc[mt2][n8][1]);
            *reinterpret_cast<__half2*>(r1 + j) =
                __floats2half2_rn(acc[mt2][n8][2], acc[mt2][n8][3]);
        }
    }
}

// ---------------------------------------------------------------------------
// Repack: out[b][o][f][n*2+k] = y[n][b*128+f][o*2+k] + bias[n][o].
// b processed in reverse (gemm grid.z == b ascending) so freshest y slices
// are L2-resident. Reads fp16 y (64B/row segments), smem pitch 273
// (conflict-free), writes full float4-coalesced out lines.
// grid (32 otiles, 8 ftiles, 32 b), 256 threads.
// ---------------------------------------------------------------------------
__global__ __launch_bounds__(256) void repack_kernel(const float* __restrict__ bias,
                                                     float* __restrict__ out) {
    __shared__ float s[8734];   // s[jl*273 + f*17 + n], jl<32, f<16, n<16
    const int o0 = blockIdx.x * 16;
    const int j0 = o0 * 2;
    const int f0 = blockIdx.y * 16;
    const int b  = 31 - blockIdx.z;   // reverse order for L2 residency
    const int tid = threadIdx.x;

    const size_t ynode = (size_t)M_TOTAL * N_PER_NODE;

    // Load 16n x 16f x 32j fp16 = 4096 half2; 16 iters x 256 threads.
    #pragma unroll
    for (int p = 0; p < 16; p++) {
        int idx = p * 256 + tid;      // 0..4095 (half2 units)
        int n = idx >> 8;
        int f = (idx >> 4) & 15;
        int h = idx & 15;             // half2 index within 32-j row
        __half2 v = *reinterpret_cast<const __half2*>(
            g_yh + n * ynode + ((size_t)b * 128 + f0 + f) * N_PER_NODE + j0 + 2 * h);
        float2 fv = __half22float2(v);
        s[(2 * h) * 273 + f * 17 + n] = fv.x;
        s[(2 * h + 1) * 273 + f * 17 + n] = fv.y;
    }
    __syncthreads();

    #pragma unroll
    for (int p = 0; p < 8; p++) {
        int idx = p * 256 + tid;      // 0..2047
        int ol = idx >> 7;            // 0..15
        int f = (idx >> 3) & 15;
        int g = idx & 7;
        int n0 = 2 * g;
        int jl = 2 * ol;
        float b0 = __ldg(bias + n0 * 512 + o0 + ol);
        float b1 = __ldg(bias + (n0 + 1) * 512 + o0 + ol);
        float4 v;
        v.x = s[jl * 273 + f * 17 + n0] + b0;
        v.y = s[(jl + 1) * 273 + f * 17 + n0] + b0;
        v.z = s[jl * 273 + f * 17 + n0 + 1] + b1;
        v.w = s[(jl + 1) * 273 + f * 17 + n0 + 1] + b1;
        size_t oaddr = (size_t)b * 2097152 + (size_t)(o0 + ol) * 4096
                     + (size_t)(f0 + f) * 32 + g * 4;
        *reinterpret_cast<float4*>(out + oaddr) = v;
    }
}

// ---------------------------------------------------------------------------
extern "C" void kernel_launch(void* const* d_in, const int* in_sizes, int n_in,
                              void* d_out, int out_size) {
    const float* x = nullptr;
    const float* W = nullptr;
    const float* bias = nullptr;
    for (int i = 0; i < n_in; i++) {
        if (in_sizes[i] == 33554432) x = (const float*)d_in[i];       // 32*512*128*16
        else if (in_sizes[i] == 8388608) W = (const float*)d_in[i];   // 16*512*512*2
        else if (in_sizes[i] == 8192) bias = (const float*)d_in[i];   // 16*512
    }
    float* out = (float*)d_out;

    split_x_kernel<<<dim3(8, 16, 32), 256>>>(x);
    split_w_kernel<<<dim3(32, 16, 16), 256>>>(W);

    cudaFuncSetAttribute(gemm_kernel, cudaFuncAttributeMaxDynamicSharedMemorySize, SMEM_BYTES);
    gemm_kernel<<<dim3(NODES, 8, 32), 256, SMEM_BYTES>>>();

    repack_kernel<<<dim3(32, 8, 32), 256>>>(bias, out);
}